// round 4
// baseline (speedup 1.0000x reference)
#include <cuda_runtime.h>

#define BB 8
#define NQV 4096
#define NKV 4096
#define CC 256
#define KNN 16
#define HH 32
#define EPSV 1e-5f
#define GR 20
#define NCELL (GR * GR * GR)
#define GMIN (-4.5f)
#define GW 0.45f
#define FINF 3.402823466e38f

// Scratch (device globals: allocation-free rule)
__device__ float    g_kvproj[BB * NKV * HH];
__device__ float    g_qterm [BB * NQV * HH];
__device__ unsigned g_topk  [BB * NQV * KNN];
__device__ unsigned g_cnt   [BB * NCELL];
__device__ unsigned g_cstart[BB * (NCELL + 1)];
__device__ unsigned g_coff  [BB * NCELL];
__device__ unsigned short g_cellid[BB * NKV];
__device__ float4   g_spts  [BB * NKV];   // reordered {x,y,z,|k|^2}
__device__ unsigned g_sidx  [BB * NKV];   // original kv index

__device__ __forceinline__ int cell_of(float x) {
    int c = (int)floorf((x - GMIN) * (1.0f / GW));
    return min(GR - 1, max(0, c));
}

// ---------------------------------------------------------------------------
// Grid build
// ---------------------------------------------------------------------------
__global__ void zero_kernel() {
    const int i = blockIdx.x * 256 + threadIdx.x;
    if (i < BB * NCELL) g_cnt[i] = 0;
}

__global__ void bin_kernel(const float* __restrict__ kxyz) {
    const int i = blockIdx.x * 512 + threadIdx.x;   // 64 x 512 = 32768
    const int b = i >> 12;
    const float x = kxyz[(size_t)i * 3 + 0];
    const float y = kxyz[(size_t)i * 3 + 1];
    const float z = kxyz[(size_t)i * 3 + 2];
    const int cid = (cell_of(z) * GR + cell_of(y)) * GR + cell_of(x);
    g_cellid[i] = (unsigned short)cid;
    atomicAdd(&g_cnt[b * NCELL + cid], 1u);
}

__global__ __launch_bounds__(1024) void scan_kernel() {
    __shared__ unsigned part[1024];
    const int b   = blockIdx.x;
    const int tid = threadIdx.x;
    const int base = tid * 8;
    unsigned loc[8], sum = 0;
#pragma unroll
    for (int j = 0; j < 8; ++j) {
        const unsigned v = (base + j < NCELL) ? g_cnt[b * NCELL + base + j] : 0u;
        loc[j] = sum;
        sum += v;
    }
    part[tid] = sum;
    __syncthreads();
    for (int off = 1; off < 1024; off <<= 1) {
        const unsigned v = (tid >= off) ? part[tid - off] : 0u;
        __syncthreads();
        part[tid] += v;
        __syncthreads();
    }
    const unsigned pre = (tid > 0) ? part[tid - 1] : 0u;
    unsigned* cst = g_cstart + (size_t)b * (NCELL + 1);
#pragma unroll
    for (int j = 0; j < 8; ++j) {
        if (base + j < NCELL) {
            cst[base + j] = pre + loc[j];
            g_coff[b * NCELL + base + j] = pre + loc[j];
        }
    }
    if (tid == 1023) cst[NCELL] = part[1023];
}

__global__ void scatter_kernel(const float* __restrict__ kxyz) {
    const int i = blockIdx.x * 512 + threadIdx.x;
    const int b = i >> 12;
    const int k = i & (NKV - 1);
    const float x = kxyz[(size_t)i * 3 + 0];
    const float y = kxyz[(size_t)i * 3 + 1];
    const float z = kxyz[(size_t)i * 3 + 2];
    const int cid = g_cellid[i];
    const unsigned pos = atomicAdd(&g_coff[b * NCELL + cid], 1u);
    g_spts[(size_t)b * NKV + pos] = make_float4(x, y, z, x * x + y * y + z * z);
    g_sidx[(size_t)b * NKV + pos] = (unsigned)k;
}

// ---------------------------------------------------------------------------
// Kernel: exact 16-NN via grid ring traversal. One thread per query.
// Ranking key d = |k|^2 - 2 q.k  (geometric bounds compared vs d + |q|^2).
// ---------------------------------------------------------------------------
__global__ __launch_bounds__(128) void knn_kernel(const float* __restrict__ qxyz)
{
    const int q = blockIdx.x * 128 + threadIdx.x;
    const int b = q >> 12;

    const float qx = qxyz[(size_t)q * 3 + 0];
    const float qy = qxyz[(size_t)q * 3 + 1];
    const float qz = qxyz[(size_t)q * 3 + 2];
    const float ax = -2.0f * qx, ay = -2.0f * qy, az = -2.0f * qz;
    const float qn = qx * qx + qy * qy + qz * qz;

    const int cx = cell_of(qx), cy = cell_of(qy), cz = cell_of(qz);
    // in-cell offsets (may exceed [0,GW] for clamped queries -> conservative)
    const float fx = qx - (GMIN + cx * GW);
    const float fy = qy - (GMIN + cy * GW);
    const float fz = qz - (GMIN + cz * GW);
    const float maxf = fmaxf(fmaxf(fmaxf(fx, GW - fx), fmaxf(fy, GW - fy)),
                             fmaxf(fz, GW - fz));

    float    s [16];
    unsigned si[16];
#pragma unroll
    for (int j = 0; j < 16; ++j) { s[j] = FINF; si[j] = 0u; }

    const float4*   sp  = g_spts + (size_t)b * NKV;
    const unsigned* sx  = g_sidx + (size_t)b * NKV;
    const unsigned* cst = g_cstart + (size_t)b * (NCELL + 1);

    for (int D = 0; D < GR; ++D) {
        if (D >= 1) {
            const float rb = (float)D * GW - maxf;  // min dist of ring D
            if (rb > 0.0f && s[15] + qn <= rb * rb) break;
        }
        for (int dz = -D; dz <= D; ++dz) {
            const int z = cz + dz;
            if (z < 0 || z >= GR) continue;
            const int adz = (dz < 0) ? -dz : dz;
            for (int dy = -D; dy <= D; ++dy) {
                const int y = cy + dy;
                if (y < 0 || y >= GR) continue;
                const int ady = (dy < 0) ? -dy : dy;
                const int step = (adz == D || ady == D) ? 1 : (2 * D > 0 ? 2 * D : 1);
                for (int dx = -D; dx <= D; dx += step) {
                    const int x = cx + dx;
                    if (x < 0 || x >= GR) continue;
                    // exact cell min-dist^2 prune
                    const float clx = GMIN + x * GW;
                    const float cly = GMIN + y * GW;
                    const float clz = GMIN + z * GW;
                    const float bx = fmaxf(0.0f, fmaxf(clx - qx, qx - (clx + GW)));
                    const float by = fmaxf(0.0f, fmaxf(cly - qy, qy - (cly + GW)));
                    const float bz = fmaxf(0.0f, fmaxf(clz - qz, qz - (clz + GW)));
                    const float cmin2 = bx * bx + by * by + bz * bz;
                    if (s[15] + qn <= cmin2) continue;

                    const int cell = (z * GR + y) * GR + x;
                    const int p0 = cst[cell], p1 = cst[cell + 1];
                    for (int j = p0; j < p1; ++j) {
                        const float4 p = sp[j];
                        float dd = fmaf(ax, p.x, p.w);
                        dd = fmaf(ay, p.y, dd);
                        dd = fmaf(az, p.z, dd);
                        if (dd < s[15]) {
                            unsigned ii = sx[j];
#pragma unroll
                            for (int k = 0; k < 16; ++k) {
                                const bool sw = dd < s[k];
                                const float    tf = s[k];
                                const unsigned ti = si[k];
                                if (sw) { s[k] = dd; si[k] = ii; dd = tf; ii = ti; }
                            }
                        }
                    }
                }
            }
        }
    }

    unsigned* o = g_topk + (size_t)q * KNN;
#pragma unroll
    for (int j = 0; j < 16; ++j) o[j] = si[j];
}

// ---------------------------------------------------------------------------
// Kernel A: projection GEMM (unchanged, known-good)
// ---------------------------------------------------------------------------
__global__ __launch_bounds__(256) void proj_kernel(
    const float* __restrict__ feat, const float* __restrict__ w1,
    const float* __restrict__ g1, const float* __restrict__ b1,
    const float* __restrict__ m1, const float* __restrict__ v1, int mode)
{
    __shared__ float AsubT[32][132];
    __shared__ float WT[32][36];

    const int tid  = threadIdx.x;
    const int row0 = blockIdx.x * 128;
    const int h0   = (tid & 7) * 4;
    const int m0   = (tid >> 3) * 4;

    float acc[4][4];
#pragma unroll
    for (int i = 0; i < 4; ++i)
#pragma unroll
        for (int j = 0; j < 4; ++j) acc[i][j] = 0.0f;

    for (int k0 = 0; k0 < CC; k0 += 32) {
        {
            const int q4 = (tid & 7) * 4;
            const int r  = tid >> 3;
#pragma unroll
            for (int j = 0; j < 4; ++j) {
                const int row = r + j * 32;
                const float4 v = *(const float4*)(feat + (size_t)(row0 + row) * CC + k0 + q4);
                AsubT[q4 + 0][row] = v.x;
                AsubT[q4 + 1][row] = v.y;
                AsubT[q4 + 2][row] = v.z;
                AsubT[q4 + 3][row] = v.w;
            }
        }
        {
            const int kk = tid & 31;
            const int hb = tid >> 5;
#pragma unroll
            for (int j = 0; j < 4; ++j) {
                const int hh = hb + j * 8;
                float w = w1[hh * (2 * CC) + k0 + kk];
                if (mode) w = w1[hh * (2 * CC) + CC + k0 + kk] - w;
                WT[kk][hh] = w;
            }
        }
        __syncthreads();
#pragma unroll
        for (int kk = 0; kk < 32; ++kk) {
            const float4 a = *(const float4*)&AsubT[kk][m0];
            const float4 w = *(const float4*)&WT[kk][h0];
            const float av[4] = {a.x, a.y, a.z, a.w};
            const float wv[4] = {w.x, w.y, w.z, w.w};
#pragma unroll
            for (int i = 0; i < 4; ++i)
#pragma unroll
                for (int j = 0; j < 4; ++j)
                    acc[i][j] = fmaf(av[i], wv[j], acc[i][j]);
        }
        __syncthreads();
    }

    float sv[4], tv[4];
#pragma unroll
    for (int j = 0; j < 4; ++j) {
        const int h = h0 + j;
        const float sc = g1[h] * rsqrtf(v1[h] + EPSV);
        sv[j] = sc;
        tv[j] = mode ? (b1[h] - m1[h] * sc) : 0.0f;
    }
    float* out = mode ? g_qterm : g_kvproj;
#pragma unroll
    for (int i = 0; i < 4; ++i) {
        float4 o;
        o.x = fmaf(acc[i][0], sv[0], tv[0]);
        o.y = fmaf(acc[i][1], sv[1], tv[1]);
        o.z = fmaf(acc[i][2], sv[2], tv[2]);
        o.w = fmaf(acc[i][3], sv[3], tv[3]);
        *(float4*)(out + (size_t)(row0 + m0 + i) * HH + h0) = o;
    }
}

// ---------------------------------------------------------------------------
// Kernel C: gather + add + leaky + max over K, then y = max @ w2^T + BN2 + leaky
// ---------------------------------------------------------------------------
__global__ __launch_bounds__(256) void fuse_kernel(
    const float* __restrict__ w2, const float* __restrict__ g2,
    const float* __restrict__ b2, const float* __restrict__ m2,
    const float* __restrict__ v2, float* __restrict__ out)
{
    __shared__ float w2t[HH][260];
    __shared__ float smaxT[HH][68];
    __shared__ float s2s[CC], t2s[CC];

    const int tid = threadIdx.x;

    for (int idx = tid; idx < CC * HH; idx += 256) {
        const int c = idx >> 5, h = idx & 31;
        w2t[h][c] = w2[idx];
    }
    {
        const float sc = g2[tid] * rsqrtf(v2[tid] + EPSV);
        s2s[tid] = sc;
        t2s[tid] = b2[tid] - m2[tid] * sc;
    }

    const int r0   = blockIdx.x * 64;
    const int b    = r0 >> 12;
    const int warp = tid >> 5, lane = tid & 31;
    const float* kvb = g_kvproj + (size_t)b * NKV * HH;

    for (int qi = warp * 8; qi < warp * 8 + 8; ++qi) {
        const int r = r0 + qi;
        const float qt = g_qterm[(size_t)r * HH + lane];
        const uint4* ip = (const uint4*)(g_topk + (size_t)r * KNN);
        const uint4 i0 = ip[0], i1 = ip[1], i2 = ip[2], i3 = ip[3];
        const unsigned id[16] = {i0.x, i0.y, i0.z, i0.w, i1.x, i1.y, i1.z, i1.w,
                                 i2.x, i2.y, i2.z, i2.w, i3.x, i3.y, i3.z, i3.w};
        float mx = -FINF;
#pragma unroll
        for (int k = 0; k < 16; ++k) {
            float v = kvb[(size_t)id[k] * HH + lane] + qt;
            v = fmaxf(v, 0.2f * v);
            mx = fmaxf(mx, v);
        }
        smaxT[lane][qi] = mx;
    }
    __syncthreads();

    const int q0 = (tid & 15) * 4;
    const int c0 = (tid >> 4) * 16;
    float acc[4][16];
#pragma unroll
    for (int i = 0; i < 4; ++i)
#pragma unroll
        for (int j = 0; j < 16; ++j) acc[i][j] = 0.0f;

#pragma unroll 8
    for (int kk = 0; kk < HH; ++kk) {
        const float4 a = *(const float4*)&smaxT[kk][q0];
        const float av[4] = {a.x, a.y, a.z, a.w};
        float bv[16];
#pragma unroll
        for (int j4 = 0; j4 < 4; ++j4) {
            const float4 t = *(const float4*)&w2t[kk][c0 + j4 * 4];
            bv[j4 * 4 + 0] = t.x; bv[j4 * 4 + 1] = t.y;
            bv[j4 * 4 + 2] = t.z; bv[j4 * 4 + 3] = t.w;
        }
#pragma unroll
        for (int i = 0; i < 4; ++i)
#pragma unroll
            for (int j = 0; j < 16; ++j)
                acc[i][j] = fmaf(av[i], bv[j], acc[i][j]);
    }

#pragma unroll
    for (int i = 0; i < 4; ++i) {
        const int r = r0 + q0 + i;
        float* op = out + (size_t)r * CC + c0;
#pragma unroll
        for (int j4 = 0; j4 < 4; ++j4) {
            float4 o;
            float y;
            y = fmaf(acc[i][j4 * 4 + 0], s2s[c0 + j4 * 4 + 0], t2s[c0 + j4 * 4 + 0]); o.x = fmaxf(y, 0.2f * y);
            y = fmaf(acc[i][j4 * 4 + 1], s2s[c0 + j4 * 4 + 1], t2s[c0 + j4 * 4 + 1]); o.y = fmaxf(y, 0.2f * y);
            y = fmaf(acc[i][j4 * 4 + 2], s2s[c0 + j4 * 4 + 2], t2s[c0 + j4 * 4 + 2]); o.z = fmaxf(y, 0.2f * y);
            y = fmaf(acc[i][j4 * 4 + 3], s2s[c0 + j4 * 4 + 3], t2s[c0 + j4 * 4 + 3]); o.w = fmaxf(y, 0.2f * y);
            *(float4*)(op + j4 * 4) = o;
        }
    }
}

// ---------------------------------------------------------------------------
extern "C" void kernel_launch(void* const* d_in, const int* in_sizes, int n_in,
                              void* d_out, int out_size)
{
    const float* qf   = (const float*)d_in[0];
    const float* qxyz = (const float*)d_in[1];
    const float* kvf  = (const float*)d_in[2];
    const float* kxyz = (const float*)d_in[3];
    const float* w1   = (const float*)d_in[4];
    const float* g1   = (const float*)d_in[5];
    const float* b1   = (const float*)d_in[6];
    const float* m1   = (const float*)d_in[7];
    const float* v1   = (const float*)d_in[8];
    const float* w2   = (const float*)d_in[9];
    const float* g2   = (const float*)d_in[10];
    const float* b2   = (const float*)d_in[11];
    const float* m2   = (const float*)d_in[12];
    const float* v2   = (const float*)d_in[13];
    float* out = (float*)d_out;

    zero_kernel<<<(BB * NCELL + 255) / 256, 256>>>();
    bin_kernel<<<64, 512>>>(kxyz);
    scan_kernel<<<BB, 1024>>>();
    scatter_kernel<<<64, 512>>>(kxyz);
    knn_kernel<<<(BB * NQV) / 128, 128>>>(qxyz);
    proj_kernel<<<256, 256>>>(kvf, w1, g1, b1, m1, v1, 0);
    proj_kernel<<<256, 256>>>(qf,  w1, g1, b1, m1, v1, 1);
    fuse_kernel<<<512, 256>>>(w2, g2, b2, m2, v2, out);
}

// round 5
// speedup vs baseline: 1.0049x; 1.0049x over previous
#include <cuda_runtime.h>

#define BB 8
#define NQV 4096
#define NKV 4096
#define CC 256
#define KNN 16
#define HH 32
#define EPSV 1e-5f
#define GR 20
#define NCELL (GR * GR * GR)
#define GMIN (-4.5f)
#define GW 0.45f
#define FINF 3.402823466e38f

// Scratch (device globals: allocation-free rule)
__device__ float    g_kvproj[BB * NKV * HH];
__device__ float    g_qterm [BB * NQV * HH];
__device__ unsigned g_topk  [BB * NQV * KNN];
// KV grid
__device__ unsigned g_cnt   [BB * NCELL];
__device__ unsigned g_cstart[BB * (NCELL + 1)];
__device__ unsigned g_coff  [BB * NCELL];
__device__ unsigned short g_cellid[BB * NKV];
__device__ float4   g_spts  [BB * NKV];   // reordered {x,y,z,|k|^2}
__device__ unsigned g_sidx  [BB * NKV];   // original kv index
// Query sort (for warp coherence)
__device__ unsigned g_qcnt  [BB * NCELL];
__device__ unsigned g_qoff  [BB * NCELL];
__device__ unsigned short g_qcellid[BB * NQV];
__device__ float4   g_qpts  [BB * NQV];   // sorted {x,y,z,|q|^2}
__device__ unsigned g_qidx  [BB * NQV];   // original query index (within batch)

__device__ __forceinline__ int cell_of(float x) {
    int c = (int)floorf((x - GMIN) * (1.0f / GW));
    return min(GR - 1, max(0, c));
}

// ---------------------------------------------------------------------------
// Grid build (kv + query binning share machinery via flag)
// ---------------------------------------------------------------------------
__global__ void zero_kernel() {
    const int i = blockIdx.x * 256 + threadIdx.x;
    if (i < BB * NCELL) { g_cnt[i] = 0; g_qcnt[i] = 0; }
}

__global__ void bin_kernel(const float* __restrict__ xyz, int isq) {
    const int i = blockIdx.x * 512 + threadIdx.x;   // 64 x 512 = 32768
    const int b = i >> 12;
    const float x = xyz[(size_t)i * 3 + 0];
    const float y = xyz[(size_t)i * 3 + 1];
    const float z = xyz[(size_t)i * 3 + 2];
    const int cid = (cell_of(z) * GR + cell_of(y)) * GR + cell_of(x);
    if (isq) {
        g_qcellid[i] = (unsigned short)cid;
        atomicAdd(&g_qcnt[b * NCELL + cid], 1u);
    } else {
        g_cellid[i] = (unsigned short)cid;
        atomicAdd(&g_cnt[b * NCELL + cid], 1u);
    }
}

__global__ __launch_bounds__(1024) void scan_kernel(int isq) {
    __shared__ unsigned part[1024];
    const int b   = blockIdx.x;
    const int tid = threadIdx.x;
    const int base = tid * 8;
    const unsigned* cnt = (isq ? g_qcnt : g_cnt) + b * NCELL;
    unsigned loc[8], sum = 0;
#pragma unroll
    for (int j = 0; j < 8; ++j) {
        const unsigned v = (base + j < NCELL) ? cnt[base + j] : 0u;
        loc[j] = sum;
        sum += v;
    }
    part[tid] = sum;
    __syncthreads();
    for (int off = 1; off < 1024; off <<= 1) {
        const unsigned v = (tid >= off) ? part[tid - off] : 0u;
        __syncthreads();
        part[tid] += v;
        __syncthreads();
    }
    const unsigned pre = (tid > 0) ? part[tid - 1] : 0u;
#pragma unroll
    for (int j = 0; j < 8; ++j) {
        if (base + j < NCELL) {
            const unsigned v = pre + loc[j];
            if (isq) {
                g_qoff[b * NCELL + base + j] = v;
            } else {
                g_cstart[(size_t)b * (NCELL + 1) + base + j] = v;
                g_coff[b * NCELL + base + j] = v;
            }
        }
    }
    if (!isq && tid == 1023) g_cstart[(size_t)b * (NCELL + 1) + NCELL] = part[1023];
}

__global__ void scatter_kernel(const float* __restrict__ xyz, int isq) {
    const int i = blockIdx.x * 512 + threadIdx.x;
    const int b = i >> 12;
    const int k = i & (NKV - 1);
    const float x = xyz[(size_t)i * 3 + 0];
    const float y = xyz[(size_t)i * 3 + 1];
    const float z = xyz[(size_t)i * 3 + 2];
    const float n2 = x * x + y * y + z * z;
    if (isq) {
        const int cid = g_qcellid[i];
        const unsigned pos = atomicAdd(&g_qoff[b * NCELL + cid], 1u);
        g_qpts[(size_t)b * NQV + pos] = make_float4(x, y, z, n2);
        g_qidx[(size_t)b * NQV + pos] = (unsigned)k;
    } else {
        const int cid = g_cellid[i];
        const unsigned pos = atomicAdd(&g_coff[b * NCELL + cid], 1u);
        g_spts[(size_t)b * NKV + pos] = make_float4(x, y, z, n2);
        g_sidx[(size_t)b * NKV + pos] = (unsigned)k;
    }
}

// ---------------------------------------------------------------------------
// Kernel: exact 16-NN via grid ring traversal. One thread per SORTED query,
// so warp lanes handle spatially adjacent queries -> coherent traversal.
// Ranking key d = |k|^2 - 2 q.k  (geometric bounds compared vs d + |q|^2).
// ---------------------------------------------------------------------------
__global__ __launch_bounds__(256) void knn_kernel()
{
    const int t = blockIdx.x * 256 + threadIdx.x;
    const int b = t >> 12;

    const float4 qp = g_qpts[t];
    const float qx = qp.x, qy = qp.y, qz = qp.z, qn = qp.w;
    const float ax = -2.0f * qx, ay = -2.0f * qy, az = -2.0f * qz;

    const int cx = cell_of(qx), cy = cell_of(qy), cz = cell_of(qz);
    const float fx = qx - (GMIN + cx * GW);
    const float fy = qy - (GMIN + cy * GW);
    const float fz = qz - (GMIN + cz * GW);
    const float maxf = fmaxf(fmaxf(fmaxf(fx, GW - fx), fmaxf(fy, GW - fy)),
                             fmaxf(fz, GW - fz));

    float    s [16];
    unsigned si[16];
#pragma unroll
    for (int j = 0; j < 16; ++j) { s[j] = FINF; si[j] = 0u; }

    const float4*   sp  = g_spts + (size_t)b * NKV;
    const unsigned* sx  = g_sidx + (size_t)b * NKV;
    const unsigned* cst = g_cstart + (size_t)b * (NCELL + 1);

    for (int D = 0; D < GR; ++D) {
        if (D >= 1) {
            const float rb = (float)D * GW - maxf;  // min dist of ring D
            if (rb > 0.0f && s[15] + qn <= rb * rb) break;
        }
        for (int dz = -D; dz <= D; ++dz) {
            const int z = cz + dz;
            if (z < 0 || z >= GR) continue;
            const int adz = (dz < 0) ? -dz : dz;
            for (int dy = -D; dy <= D; ++dy) {
                const int y = cy + dy;
                if (y < 0 || y >= GR) continue;
                const int ady = (dy < 0) ? -dy : dy;
                const int step = (adz == D || ady == D) ? 1 : (2 * D > 0 ? 2 * D : 1);
                for (int dx = -D; dx <= D; dx += step) {
                    const int x = cx + dx;
                    if (x < 0 || x >= GR) continue;
                    const float clx = GMIN + x * GW;
                    const float cly = GMIN + y * GW;
                    const float clz = GMIN + z * GW;
                    const float bx = fmaxf(0.0f, fmaxf(clx - qx, qx - (clx + GW)));
                    const float by = fmaxf(0.0f, fmaxf(cly - qy, qy - (cly + GW)));
                    const float bz = fmaxf(0.0f, fmaxf(clz - qz, qz - (clz + GW)));
                    const float cmin2 = bx * bx + by * by + bz * bz;
                    if (s[15] + qn <= cmin2) continue;

                    const int cell = (z * GR + y) * GR + x;
                    const int p0 = cst[cell], p1 = cst[cell + 1];
                    for (int j = p0; j < p1; ++j) {
                        const float4 p = sp[j];
                        float dd = fmaf(ax, p.x, p.w);
                        dd = fmaf(ay, p.y, dd);
                        dd = fmaf(az, p.z, dd);
                        if (dd < s[15]) {
                            unsigned ii = sx[j];
#pragma unroll
                            for (int k = 0; k < 16; ++k) {
                                const bool sw = dd < s[k];
                                const float    tf = s[k];
                                const unsigned ti = si[k];
                                if (sw) { s[k] = dd; si[k] = ii; dd = tf; ii = ti; }
                            }
                        }
                    }
                }
            }
        }
    }

    const int q = (b << 12) + g_qidx[t];
    unsigned* o = g_topk + (size_t)q * KNN;
#pragma unroll
    for (int j = 0; j < 16; ++j) o[j] = si[j];
}

// ---------------------------------------------------------------------------
// Kernel A: projection GEMM (unchanged, known-good)
// ---------------------------------------------------------------------------
__global__ __launch_bounds__(256) void proj_kernel(
    const float* __restrict__ feat, const float* __restrict__ w1,
    const float* __restrict__ g1, const float* __restrict__ b1,
    const float* __restrict__ m1, const float* __restrict__ v1, int mode)
{
    __shared__ float AsubT[32][132];
    __shared__ float WT[32][36];

    const int tid  = threadIdx.x;
    const int row0 = blockIdx.x * 128;
    const int h0   = (tid & 7) * 4;
    const int m0   = (tid >> 3) * 4;

    float acc[4][4];
#pragma unroll
    for (int i = 0; i < 4; ++i)
#pragma unroll
        for (int j = 0; j < 4; ++j) acc[i][j] = 0.0f;

    for (int k0 = 0; k0 < CC; k0 += 32) {
        {
            const int q4 = (tid & 7) * 4;
            const int r  = tid >> 3;
#pragma unroll
            for (int j = 0; j < 4; ++j) {
                const int row = r + j * 32;
                const float4 v = *(const float4*)(feat + (size_t)(row0 + row) * CC + k0 + q4);
                AsubT[q4 + 0][row] = v.x;
                AsubT[q4 + 1][row] = v.y;
                AsubT[q4 + 2][row] = v.z;
                AsubT[q4 + 3][row] = v.w;
            }
        }
        {
            const int kk = tid & 31;
            const int hb = tid >> 5;
#pragma unroll
            for (int j = 0; j < 4; ++j) {
                const int hh = hb + j * 8;
                float w = w1[hh * (2 * CC) + k0 + kk];
                if (mode) w = w1[hh * (2 * CC) + CC + k0 + kk] - w;
                WT[kk][hh] = w;
            }
        }
        __syncthreads();
#pragma unroll
        for (int kk = 0; kk < 32; ++kk) {
            const float4 a = *(const float4*)&AsubT[kk][m0];
            const float4 w = *(const float4*)&WT[kk][h0];
            const float av[4] = {a.x, a.y, a.z, a.w};
            const float wv[4] = {w.x, w.y, w.z, w.w};
#pragma unroll
            for (int i = 0; i < 4; ++i)
#pragma unroll
                for (int j = 0; j < 4; ++j)
                    acc[i][j] = fmaf(av[i], wv[j], acc[i][j]);
        }
        __syncthreads();
    }

    float sv[4], tv[4];
#pragma unroll
    for (int j = 0; j < 4; ++j) {
        const int h = h0 + j;
        const float sc = g1[h] * rsqrtf(v1[h] + EPSV);
        sv[j] = sc;
        tv[j] = mode ? (b1[h] - m1[h] * sc) : 0.0f;
    }
    float* out = mode ? g_qterm : g_kvproj;
#pragma unroll
    for (int i = 0; i < 4; ++i) {
        float4 o;
        o.x = fmaf(acc[i][0], sv[0], tv[0]);
        o.y = fmaf(acc[i][1], sv[1], tv[1]);
        o.z = fmaf(acc[i][2], sv[2], tv[2]);
        o.w = fmaf(acc[i][3], sv[3], tv[3]);
        *(float4*)(out + (size_t)(row0 + m0 + i) * HH + h0) = o;
    }
}

// ---------------------------------------------------------------------------
// Kernel C: gather + add + leaky + max over K, then y = max @ w2^T + BN2 + leaky
// ---------------------------------------------------------------------------
__global__ __launch_bounds__(256) void fuse_kernel(
    const float* __restrict__ w2, const float* __restrict__ g2,
    const float* __restrict__ b2, const float* __restrict__ m2,
    const float* __restrict__ v2, float* __restrict__ out)
{
    __shared__ float w2t[HH][260];
    __shared__ float smaxT[HH][68];
    __shared__ float s2s[CC], t2s[CC];

    const int tid = threadIdx.x;

    for (int idx = tid; idx < CC * HH; idx += 256) {
        const int c = idx >> 5, h = idx & 31;
        w2t[h][c] = w2[idx];
    }
    {
        const float sc = g2[tid] * rsqrtf(v2[tid] + EPSV);
        s2s[tid] = sc;
        t2s[tid] = b2[tid] - m2[tid] * sc;
    }

    const int r0   = blockIdx.x * 64;
    const int b    = r0 >> 12;
    const int warp = tid >> 5, lane = tid & 31;
    const float* kvb = g_kvproj + (size_t)b * NKV * HH;

    for (int qi = warp * 8; qi < warp * 8 + 8; ++qi) {
        const int r = r0 + qi;
        const float qt = g_qterm[(size_t)r * HH + lane];
        const uint4* ip = (const uint4*)(g_topk + (size_t)r * KNN);
        const uint4 i0 = ip[0], i1 = ip[1], i2 = ip[2], i3 = ip[3];
        const unsigned id[16] = {i0.x, i0.y, i0.z, i0.w, i1.x, i1.y, i1.z, i1.w,
                                 i2.x, i2.y, i2.z, i2.w, i3.x, i3.y, i3.z, i3.w};
        float mx = -FINF;
#pragma unroll
        for (int k = 0; k < 16; ++k) {
            float v = kvb[(size_t)id[k] * HH + lane] + qt;
            v = fmaxf(v, 0.2f * v);
            mx = fmaxf(mx, v);
        }
        smaxT[lane][qi] = mx;
    }
    __syncthreads();

    const int q0 = (tid & 15) * 4;
    const int c0 = (tid >> 4) * 16;
    float acc[4][16];
#pragma unroll
    for (int i = 0; i < 4; ++i)
#pragma unroll
        for (int j = 0; j < 16; ++j) acc[i][j] = 0.0f;

#pragma unroll 8
    for (int kk = 0; kk < HH; ++kk) {
        const float4 a = *(const float4*)&smaxT[kk][q0];
        const float av[4] = {a.x, a.y, a.z, a.w};
        float bv[16];
#pragma unroll
        for (int j4 = 0; j4 < 4; ++j4) {
            const float4 t = *(const float4*)&w2t[kk][c0 + j4 * 4];
            bv[j4 * 4 + 0] = t.x; bv[j4 * 4 + 1] = t.y;
            bv[j4 * 4 + 2] = t.z; bv[j4 * 4 + 3] = t.w;
        }
#pragma unroll
        for (int i = 0; i < 4; ++i)
#pragma unroll
            for (int j = 0; j < 16; ++j)
                acc[i][j] = fmaf(av[i], bv[j], acc[i][j]);
    }

#pragma unroll
    for (int i = 0; i < 4; ++i) {
        const int r = r0 + q0 + i;
        float* op = out + (size_t)r * CC + c0;
#pragma unroll
        for (int j4 = 0; j4 < 4; ++j4) {
            float4 o;
            float y;
            y = fmaf(acc[i][j4 * 4 + 0], s2s[c0 + j4 * 4 + 0], t2s[c0 + j4 * 4 + 0]); o.x = fmaxf(y, 0.2f * y);
            y = fmaf(acc[i][j4 * 4 + 1], s2s[c0 + j4 * 4 + 1], t2s[c0 + j4 * 4 + 1]); o.y = fmaxf(y, 0.2f * y);
            y = fmaf(acc[i][j4 * 4 + 2], s2s[c0 + j4 * 4 + 2], t2s[c0 + j4 * 4 + 2]); o.z = fmaxf(y, 0.2f * y);
            y = fmaf(acc[i][j4 * 4 + 3], s2s[c0 + j4 * 4 + 3], t2s[c0 + j4 * 4 + 3]); o.w = fmaxf(y, 0.2f * y);
            *(float4*)(op + j4 * 4) = o;
        }
    }
}

// ---------------------------------------------------------------------------
extern "C" void kernel_launch(void* const* d_in, const int* in_sizes, int n_in,
                              void* d_out, int out_size)
{
    const float* qf   = (const float*)d_in[0];
    const float* qxyz = (const float*)d_in[1];
    const float* kvf  = (const float*)d_in[2];
    const float* kxyz = (const float*)d_in[3];
    const float* w1   = (const float*)d_in[4];
    const float* g1   = (const float*)d_in[5];
    const float* b1   = (const float*)d_in[6];
    const float* m1   = (const float*)d_in[7];
    const float* v1   = (const float*)d_in[8];
    const float* w2   = (const float*)d_in[9];
    const float* g2   = (const float*)d_in[10];
    const float* b2   = (const float*)d_in[11];
    const float* m2   = (const float*)d_in[12];
    const float* v2   = (const float*)d_in[13];
    float* out = (float*)d_out;

    zero_kernel<<<(BB * NCELL + 255) / 256, 256>>>();
    bin_kernel<<<64, 512>>>(kxyz, 0);
    bin_kernel<<<64, 512>>>(qxyz, 1);
    scan_kernel<<<BB, 1024>>>(0);
    scan_kernel<<<BB, 1024>>>(1);
    scatter_kernel<<<64, 512>>>(kxyz, 0);
    scatter_kernel<<<64, 512>>>(qxyz, 1);
    knn_kernel<<<(BB * NQV) / 256, 256>>>();
    proj_kernel<<<256, 256>>>(kvf, w1, g1, b1, m1, v1, 0);
    proj_kernel<<<256, 256>>>(qf,  w1, g1, b1, m1, v1, 1);
    fuse_kernel<<<512, 256>>>(w2, g2, b2, m2, v2, out);
}